// round 15
// baseline (speedup 1.0000x reference)
#include <cuda_runtime.h>
#include <cuda_fp16.h>
#include <cstdint>

#define BATCH   512
#define MEM     256            // K dimension
#define FEAT    512
#define NCOL    131072         // 64*2048
#define TOPK    16

#define NCHUNK  128            // N columns per gemm work item
#define NCHUNKS (NCOL / NCHUNK)     // 1024
#define MTILE   256            // M rows per gemm CTA (one half)
#define GT      512            // gemm threads (16 warps)

#define BPAD    136            // halfs per B k-row in smem (128 + 8)
#define B_SLAB  (64 * BPAD)    // halfs per 64-K fp16 B slab (8704)
#define A_HALFS (MTILE * MEM)  // 65536 halfs = 131072 B, swizzled, no pad
#define DYN_SMEM ((A_HALFS + 2 * B_SLAB) * 2)   // 165888 bytes

#define TB      8              // batches per topk block
#define TBLOCKS (BATCH / TB)   // 64

// Dense fp16 weight matrix W[512][256] (built by topk kernel)
__device__ __align__(16) __half g_W[BATCH * MEM];

// ---------------------------------------------------------------------------
// Kernel 1: cosine sim + top-16 + clamp + renormalize -> dense fp16 W.
// 64 blocks x 256 threads, 8 batches per block (halves keys L2 traffic vs
// the 128-block version). Thread t owns key row t (8 batch accumulators);
// warp w does batch w's register-resident top-16.
// ---------------------------------------------------------------------------
__global__ void __launch_bounds__(256)
topk_kernel(const float* __restrict__ features, const float* __restrict__ keys) {
    __shared__ float f_s[TB * FEAT];          // 16 KB
    __shared__ float fn_s[TB];
    __shared__ float sim_s[TB * 264];         // 8.25 KB
    __shared__ float topv_s[TB][TOPK];
    __shared__ int   topi_s[TB][TOPK];
    __shared__ float w_dense[TB][MEM];        // 8 KB

    const int t    = threadIdx.x;
    const int warp = t >> 5;
    const int lane = t & 31;
    const int base = blockIdx.x * TB;

    // stage 8 feature rows (1024 float4)
    float4* f4s = reinterpret_cast<float4*>(f_s);
    const float4* fg = reinterpret_cast<const float4*>(features) + (size_t)base * (FEAT / 4);
    for (int i = t; i < TB * FEAT / 4; i += 256) f4s[i] = fg[i];
    __syncthreads();

    // feature norms: warp w computes ||f_w||
    {
        float s = 0.f;
#pragma unroll
        for (int m = 0; m < FEAT / 32; m++) {
            float v = f_s[warp * FEAT + lane + m * 32];
            s += v * v;
        }
#pragma unroll
        for (int off = 16; off; off >>= 1) s += __shfl_down_sync(0xffffffffu, s, off);
        if (lane == 0) fn_s[warp] = fmaxf(sqrtf(s), 1e-8f);
    }
    __syncthreads();

    // dots: thread t owns key row t
    const float4* krow = reinterpret_cast<const float4*>(keys) + (size_t)t * (FEAT / 4);
    float acc[TB];
#pragma unroll
    for (int b = 0; b < TB; b++) acc[b] = 0.f;
    float kn = 0.f;
#pragma unroll 2
    for (int dd = 0; dd < FEAT / 4; dd++) {
        float4 kv = krow[dd];
        kn += kv.x * kv.x + kv.y * kv.y + kv.z * kv.z + kv.w * kv.w;
#pragma unroll
        for (int b = 0; b < TB; b++) {
            float4 fv = f4s[b * (FEAT / 4) + dd];
            acc[b] += kv.x * fv.x + kv.y * fv.y + kv.z * fv.z + kv.w * fv.w;
        }
    }
    const float rkn = fmaxf(sqrtf(kn), 1e-8f);
#pragma unroll
    for (int b = 0; b < TB; b++)
        sim_s[b * 264 + t] = acc[b] / (fn_s[b] * rkn);

    // zero dense weights
#pragma unroll
    for (int r = 0; r < TB; r++) w_dense[r][t] = 0.f;
    __syncthreads();

    // per-warp top-16: warp w handles batch w (8 warps, 8 batches)
    {
        float v[8];
#pragma unroll
        for (int m = 0; m < 8; m++) v[m] = sim_s[warp * 264 + lane * 8 + m];

        for (int k = 0; k < TOPK; k++) {
            float best = v[0];
            int bm = 0;
#pragma unroll
            for (int m = 1; m < 8; m++)
                if (v[m] > best) { best = v[m]; bm = m; }
            int gi = lane * 8 + bm;
#pragma unroll
            for (int off = 16; off; off >>= 1) {
                float ov = __shfl_down_sync(0xffffffffu, best, off);
                int   oi = __shfl_down_sync(0xffffffffu, gi,   off);
                if (ov > best || (ov == best && oi < gi)) { best = ov; gi = oi; }
            }
            best = __shfl_sync(0xffffffffu, best, 0);
            gi   = __shfl_sync(0xffffffffu, gi,   0);
            if (lane == (gi >> 3)) {
                int li = gi & 7;
#pragma unroll
                for (int m = 0; m < 8; m++)
                    if (m == li) v[m] = -3.0e38f;
            }
            if (lane == 0) { topv_s[warp][k] = best; topi_s[warp][k] = gi; }
        }
        __syncwarp();

        float tv = (lane < TOPK) ? fmaxf(topv_s[warp][lane], 0.f) : 0.f;
        float s = tv;
#pragma unroll
        for (int off = 16; off; off >>= 1) s += __shfl_down_sync(0xffffffffu, s, off);
        s = __shfl_sync(0xffffffffu, s, 0);
        const float inv = 1.0f / s;   // s==0 -> inf; 0*inf=NaN matches ref 0/0
        if (lane < TOPK)
            w_dense[warp][topi_s[warp][lane]] = tv * inv;
    }
    __syncthreads();

    // emit linear fp16 W rows
#pragma unroll
    for (int r = 0; r < TB; r++)
        g_W[(base + r) * MEM + t] = __float2half_rn(w_dense[r][t]);
}

// ---------------------------------------------------------------------------
// Kernel 2: persistent HMMA GEMM (byte-for-byte R12: 16 warps, warp tile
// 64M x 32N, CTA 256M x 128N). A loaded once (XOR-swizzled, cp.async);
// B slabs staged fp32->fp16 in-loop with 2-ks LDG windows + L2 prefetch;
// CTA pairs (2p,2p+1) walk identical chunk lists => B's 2nd read hits L2.
// ---------------------------------------------------------------------------
__device__ __forceinline__ void mma16816(float d[4],
                                         uint32_t a0, uint32_t a1, uint32_t a2, uint32_t a3,
                                         uint32_t b0, uint32_t b1) {
    asm volatile(
        "mma.sync.aligned.m16n8k16.row.col.f32.f16.f16.f32 "
        "{%0,%1,%2,%3}, {%4,%5,%6,%7}, {%8,%9}, {%0,%1,%2,%3};"
        : "+f"(d[0]), "+f"(d[1]), "+f"(d[2]), "+f"(d[3])
        : "r"(a0), "r"(a1), "r"(a2), "r"(a3), "r"(b0), "r"(b1));
}
__device__ __forceinline__ void ldsm_x4(uint32_t r[4], uint32_t sa) {
    asm volatile("ldmatrix.sync.aligned.m8n8.x4.shared.b16 {%0,%1,%2,%3}, [%4];"
        : "=r"(r[0]), "=r"(r[1]), "=r"(r[2]), "=r"(r[3]) : "r"(sa));
}
__device__ __forceinline__ void ldsm_x4_t(uint32_t r[4], uint32_t sa) {
    asm volatile("ldmatrix.sync.aligned.m8n8.x4.trans.shared.b16 {%0,%1,%2,%3}, [%4];"
        : "=r"(r[0]), "=r"(r[1]), "=r"(r[2]), "=r"(r[3]) : "r"(sa));
}
__device__ __forceinline__ void stg_cs_v2(float* p, float2 v) {
    asm volatile("st.global.cs.v2.f32 [%0], {%1, %2};" :: "l"(p), "f"(v.x), "f"(v.y) : "memory");
}
__device__ __forceinline__ void prefetch_l2(const void* p) {
    asm volatile("prefetch.global.L2 [%0];" :: "l"(p));
}

__global__ void __launch_bounds__(GT, 1)
gemm_kernel(const float* __restrict__ memory, float* __restrict__ out, int pairs) {
    extern __shared__ __half sm[];
    __half* As = sm;                    // [256][256] swizzled (no pad)
    __half* Bs = sm + A_HALFS;          // [2][64][BPAD]

    const int tid   = threadIdx.x;
    const int warp  = tid >> 5;
    const int lane  = tid & 31;
    const int g     = lane >> 2;
    const int tg    = lane & 3;
    const int gl    = lane >> 4;
    const int mhalf = blockIdx.x & 1;
    const int pidx  = blockIdx.x >> 1;

    const int mw = (warp >> 2) * 64;    // 4 M stripes of 64
    const int nw = (warp & 3) * 32;     // 4 N stripes of 32

    const uint32_t As_base = (uint32_t)__cvta_generic_to_shared(As);
    const uint32_t Bs_base = (uint32_t)__cvta_generic_to_shared(Bs);

    // ---- load A once (cp.async, XOR-swizzled) ----
    {
        const __half* srcA = g_W + (size_t)(mhalf * MTILE) * MEM;
#pragma unroll
        for (int j = 0; j < 16; j++) {
            int i = tid + j * GT;                // 8192 granules of 16B
            int m = i >> 5, gs = i & 31;
            uint32_t sa = As_base + (uint32_t)(m * 512 + ((gs ^ (m & 7)) << 4));
            const __half* gp = srcA + m * MEM + gs * 8;
            asm volatile("cp.async.cg.shared.global [%0], [%1], 16;" :: "r"(sa), "l"(gp) : "memory");
        }
        asm volatile("cp.async.commit_group;" ::: "memory");
    }

    const int nch   = (NCHUNKS - pidx + pairs - 1) / pairs;
    const int total = nch * 4;           // 64-K slabs for this CTA

    // ---- B staging: slab = 64 rows x 128 cols fp32 = 2048 float4 ----
    const float4* membase = reinterpret_cast<const float4*>(memory);
    float4 br[2];

    auto ldg_half = [&](int tt, int h) {
        const int c  = pidx + (tt >> 2) * pairs;
        const int kc = tt & 3;
        const float4* src = membase + (size_t)(kc * 64) * (NCOL / 4) + (size_t)c * 32;
#pragma unroll
        for (int q = 0; q < 2; q++) {
            int i = tid + (q + 2 * h) * GT;
            br[q] = __ldg(&src[(size_t)(i >> 5) * (NCOL / 4) + (i & 31)]);
        }
    };
    auto sts_half = [&](int tt, int h) {
        const int buf = tt & 1;
#pragma unroll
        for (int q = 0; q < 2; q++) {
            int i = tid + (q + 2 * h) * GT;
            int r = i >> 5, c4 = i & 31;
            __half2 h0 = __floats2half2_rn(br[q].x, br[q].y);
            __half2 h1 = __floats2half2_rn(br[q].z, br[q].w);
            uint2* dp = reinterpret_cast<uint2*>(Bs + buf * B_SLAB + r * BPAD + c4 * 4);
            *dp = make_uint2(*reinterpret_cast<uint32_t*>(&h0),
                             *reinterpret_cast<uint32_t*>(&h1));
        }
    };
    auto prefetch_slab = [&](int tt) {
        const int c  = pidx + (tt >> 2) * pairs;
        const int kc = tt & 3;
        const float* p = memory + (size_t)(kc * 64 + (tid >> 3)) * NCOL
                       + (size_t)c * NCHUNK + (tid & 7) * 16;
        prefetch_l2(p);
    };

    // ---- prologue: stage slab 0 fully, pre-issue ldg(1,h0), wait A ----
    ldg_half(0, 0); sts_half(0, 0);
    ldg_half(0, 1); sts_half(0, 1);
    if (total > 1) ldg_half(1, 0);
    if (total > 2) prefetch_slab(2);
    asm volatile("cp.async.wait_group 0;" ::: "memory");
    __syncthreads();

    // A fragment row bases (swizzle applied per-k at use)
    uint32_t a_row[4], am7[4];
#pragma unroll
    for (int mi = 0; mi < 4; mi++) {
        int m = mw + mi * 16 + (lane & 15);
        a_row[mi] = As_base + (uint32_t)(m * 512);
        am7[mi]   = (uint32_t)(m & 7);
    }
    // B ldmatrix lane offset (bytes within a slab)
    const int bgrp = lane >> 3;
    const uint32_t b_lane_off =
        (uint32_t)(((bgrp & 1) * 8 + (lane & 7)) * (BPAD * 2) + (nw + (bgrp >> 1) * 8) * 2);

    float d[4][4][4];
#pragma unroll
    for (int mi = 0; mi < 4; mi++)
#pragma unroll
        for (int ni = 0; ni < 4; ni++)
#pragma unroll
            for (int r = 0; r < 4; r++) d[mi][ni][r] = 0.f;

    int c = pidx;
    for (int t = 0; t < total; t++) {
        const int  kc   = t & 3;
        const bool more = (t + 1 < total);
        const uint32_t bbase = Bs_base + (uint32_t)((t & 1) * B_SLAB * 2) + b_lane_off;

#pragma unroll
        for (int ks = 0; ks < 4; ks++) {
            // staging schedule: every LDG gets a 2-ks window; slabs are
            // L2-prefetched 3 ahead so LDG hits L2 (~250cyc << window).
            if (ks == 0 && more) { sts_half(t + 1, 0); ldg_half(t + 1, 1); }
            if (ks == 1 && t + 3 < total) prefetch_slab(t + 3);
            if (ks == 2 && more) { sts_half(t + 1, 1); if (t + 2 < total) ldg_half(t + 2, 0); }

            uint32_t bf[8];
            ldsm_x4_t(bf,     bbase + ks * (16 * BPAD * 2));
            ldsm_x4_t(bf + 4, bbase + ks * (16 * BPAD * 2) + 32);
            const uint32_t gk = (uint32_t)(kc * 8 + ks * 2 + gl);
#pragma unroll
            for (int mi = 0; mi < 4; mi++) {
                uint32_t a[4];
                ldsm_x4(a, a_row[mi] + ((gk ^ am7[mi]) << 4));
                mma16816(d[mi][0], a[0], a[1], a[2], a[3], bf[0], bf[1]);
                mma16816(d[mi][1], a[0], a[1], a[2], a[3], bf[2], bf[3]);
                mma16816(d[mi][2], a[0], a[1], a[2], a[3], bf[4], bf[5]);
                mma16816(d[mi][3], a[0], a[1], a[2], a[3], bf[6], bf[7]);
            }
        }

        if (kc == 3) {
            // epilogue for chunk c: streaming stores, reset accumulators
            const size_t cbase = (size_t)c * NCHUNK;
            const int mbase = mhalf * MTILE;
#pragma unroll
            for (int mi = 0; mi < 4; mi++) {
                const int r0 = mbase + mw + mi * 16 + g;
#pragma unroll
                for (int ni = 0; ni < 4; ni++) {
                    const size_t col = cbase + nw + ni * 8 + tg * 2;
                    stg_cs_v2(out + (size_t)r0 * NCOL + col,
                              make_float2(d[mi][ni][0], d[mi][ni][1]));
                    stg_cs_v2(out + (size_t)(r0 + 8) * NCOL + col,
                              make_float2(d[mi][ni][2], d[mi][ni][3]));
#pragma unroll
                    for (int r = 0; r < 4; r++) d[mi][ni][r] = 0.f;
                }
            }
            c += pairs;
        }

        __syncthreads();   // next slab's fp16 buffer fully written
    }
}

// ---------------------------------------------------------------------------
extern "C" void kernel_launch(void* const* d_in, const int* in_sizes, int n_in,
                              void* d_out, int out_size) {
    const float* features = (const float*)d_in[0];
    const float* keys     = (const float*)d_in[1];
    const float* memory   = (const float*)d_in[2];
    float*       out      = (float*)d_out;

    int sms = 148;
    cudaDeviceGetAttribute(&sms, cudaDevAttrMultiProcessorCount, 0);

    cudaFuncSetAttribute(gemm_kernel,
                         cudaFuncAttributeMaxDynamicSharedMemorySize, DYN_SMEM);

    topk_kernel<<<TBLOCKS, 256>>>(features, keys);
    gemm_kernel<<<2 * sms, GT, DYN_SMEM>>>(memory, out, sms);
}

// round 16
// speedup vs baseline: 1.0448x; 1.0448x over previous
#include <cuda_runtime.h>
#include <cuda_fp16.h>
#include <cstdint>

#define BATCH   512
#define MEM     256            // K dimension
#define FEAT    512
#define NCOL    131072         // 64*2048
#define TOPK    16

#define NCHUNK  128            // N columns per gemm work item
#define NCHUNKS (NCOL / NCHUNK)     // 1024
#define MTILE   256            // M rows per gemm CTA (one half)
#define GT      512            // gemm threads (16 warps)

#define BPAD    136            // halfs per B k-row in smem (128 + 8)
#define B_SLAB  (64 * BPAD)    // halfs per 64-K fp16 B slab (8704)
#define A_HALFS (MTILE * MEM)  // 65536 halfs = 131072 B, swizzled, no pad
#define DYN_SMEM ((A_HALFS + 2 * B_SLAB) * 2)   // 165888 bytes

// Dense fp16 weight matrix W[512][256] (built by topk kernel)
__device__ __align__(16) __half g_W[BATCH * MEM];

// ---------------------------------------------------------------------------
// Kernel 1: cosine sim + top-16 + clamp + renormalize -> dense fp16 W.
// R12 shape (128 blocks x 256 threads, 4 batches/block) + deeper LDG MLP.
// Signals PDL completion after W is written.
// ---------------------------------------------------------------------------
__global__ void __launch_bounds__(256)
topk_kernel(const float* __restrict__ features, const float* __restrict__ keys) {
    __shared__ float f_s[4 * FEAT];
    __shared__ float fn_s[4];
    __shared__ float sim_s[4 * 264];
    __shared__ float topv_s[4][TOPK];
    __shared__ int   topi_s[4][TOPK];
    __shared__ float w_dense[4][MEM];

    const int t    = threadIdx.x;
    const int warp = t >> 5;
    const int lane = t & 31;
    const int base = blockIdx.x * 4;

    float4* f4s = reinterpret_cast<float4*>(f_s);
    const float4* fg = reinterpret_cast<const float4*>(features) + (size_t)base * (FEAT / 4);
    for (int i = t; i < 4 * FEAT / 4; i += 256) f4s[i] = fg[i];
    __syncthreads();

    if (warp < 4) {
        float s = 0.f;
#pragma unroll
        for (int m = 0; m < FEAT / 32; m++) {
            float v = f_s[warp * FEAT + lane + m * 32];
            s += v * v;
        }
#pragma unroll
        for (int off = 16; off; off >>= 1) s += __shfl_down_sync(0xffffffffu, s, off);
        if (lane == 0) fn_s[warp] = fmaxf(sqrtf(s), 1e-8f);
    }
    __syncthreads();

    const float4* krow = reinterpret_cast<const float4*>(keys) + (size_t)t * (FEAT / 4);
    float acc[4] = {0.f, 0.f, 0.f, 0.f};
    float kn = 0.f;
#pragma unroll 8
    for (int dd = 0; dd < FEAT / 4; dd++) {
        float4 kv = krow[dd];
        kn += kv.x * kv.x + kv.y * kv.y + kv.z * kv.z + kv.w * kv.w;
#pragma unroll
        for (int b = 0; b < 4; b++) {
            float4 fv = f4s[b * (FEAT / 4) + dd];
            acc[b] += kv.x * fv.x + kv.y * fv.y + kv.z * fv.z + kv.w * fv.w;
        }
    }
    const float rkn = fmaxf(sqrtf(kn), 1e-8f);
#pragma unroll
    for (int b = 0; b < 4; b++)
        sim_s[b * 264 + t] = acc[b] / (fn_s[b] * rkn);

#pragma unroll
    for (int r = 0; r < 4; r++) w_dense[r][t] = 0.f;
    __syncthreads();

    if (warp < 4) {
        float v[8];
#pragma unroll
        for (int m = 0; m < 8; m++) v[m] = sim_s[warp * 264 + lane * 8 + m];

        for (int k = 0; k < TOPK; k++) {
            float best = v[0];
            int bm = 0;
#pragma unroll
            for (int m = 1; m < 8; m++)
                if (v[m] > best) { best = v[m]; bm = m; }
            int gi = lane * 8 + bm;
#pragma unroll
            for (int off = 16; off; off >>= 1) {
                float ov = __shfl_down_sync(0xffffffffu, best, off);
                int   oi = __shfl_down_sync(0xffffffffu, gi,   off);
                if (ov > best || (ov == best && oi < gi)) { best = ov; gi = oi; }
            }
            best = __shfl_sync(0xffffffffu, best, 0);
            gi   = __shfl_sync(0xffffffffu, gi,   0);
            if (lane == (gi >> 3)) {
                int li = gi & 7;
#pragma unroll
                for (int m = 0; m < 8; m++)
                    if (m == li) v[m] = -3.0e38f;
            }
            if (lane == 0) { topv_s[warp][k] = best; topi_s[warp][k] = gi; }
        }
        __syncwarp();

        float tv = (lane < TOPK) ? fmaxf(topv_s[warp][lane], 0.f) : 0.f;
        float s = tv;
#pragma unroll
        for (int off = 16; off; off >>= 1) s += __shfl_down_sync(0xffffffffu, s, off);
        s = __shfl_sync(0xffffffffu, s, 0);
        const float inv = 1.0f / s;   // s==0 -> inf; 0*inf=NaN matches ref 0/0
        if (lane < TOPK)
            w_dense[warp][topi_s[warp][lane]] = tv * inv;
    }
    __syncthreads();

#pragma unroll
    for (int r = 0; r < 4; r++)
        g_W[(base + r) * MEM + t] = __float2half_rn(w_dense[r][t]);

    // PDL: make W visible, then allow the dependent gemm grid to proceed.
    __threadfence();
    __syncthreads();
    asm volatile("griddepcontrol.launch_dependents;" ::: "memory");
}

// ---------------------------------------------------------------------------
// Kernel 2: persistent HMMA GEMM (R12 mainloop). Launched with PDL:
// CTAs start while topk drains, run the g_W-independent B prologue,
// griddepcontrol.wait, then load A and enter the mainloop.
// ---------------------------------------------------------------------------
__device__ __forceinline__ void mma16816(float d[4],
                                         uint32_t a0, uint32_t a1, uint32_t a2, uint32_t a3,
                                         uint32_t b0, uint32_t b1) {
    asm volatile(
        "mma.sync.aligned.m16n8k16.row.col.f32.f16.f16.f32 "
        "{%0,%1,%2,%3}, {%4,%5,%6,%7}, {%8,%9}, {%0,%1,%2,%3};"
        : "+f"(d[0]), "+f"(d[1]), "+f"(d[2]), "+f"(d[3])
        : "r"(a0), "r"(a1), "r"(a2), "r"(a3), "r"(b0), "r"(b1));
}
__device__ __forceinline__ void ldsm_x4(uint32_t r[4], uint32_t sa) {
    asm volatile("ldmatrix.sync.aligned.m8n8.x4.shared.b16 {%0,%1,%2,%3}, [%4];"
        : "=r"(r[0]), "=r"(r[1]), "=r"(r[2]), "=r"(r[3]) : "r"(sa));
}
__device__ __forceinline__ void ldsm_x4_t(uint32_t r[4], uint32_t sa) {
    asm volatile("ldmatrix.sync.aligned.m8n8.x4.trans.shared.b16 {%0,%1,%2,%3}, [%4];"
        : "=r"(r[0]), "=r"(r[1]), "=r"(r[2]), "=r"(r[3]) : "r"(sa));
}
__device__ __forceinline__ void stg_cs_v2(float* p, float2 v) {
    asm volatile("st.global.cs.v2.f32 [%0], {%1, %2};" :: "l"(p), "f"(v.x), "f"(v.y) : "memory");
}
__device__ __forceinline__ void prefetch_l2(const void* p) {
    asm volatile("prefetch.global.L2 [%0];" :: "l"(p));
}

__global__ void __launch_bounds__(GT, 1)
gemm_kernel(const float* __restrict__ memory, float* __restrict__ out, int pairs) {
    extern __shared__ __half sm[];
    __half* As = sm;                    // [256][256] swizzled (no pad)
    __half* Bs = sm + A_HALFS;          // [2][64][BPAD]

    const int tid   = threadIdx.x;
    const int warp  = tid >> 5;
    const int lane  = tid & 31;
    const int g     = lane >> 2;
    const int tg    = lane & 3;
    const int gl    = lane >> 4;
    const int mhalf = blockIdx.x & 1;
    const int pidx  = blockIdx.x >> 1;

    const int mw = (warp >> 2) * 64;    // 4 M stripes of 64
    const int nw = (warp & 3) * 32;     // 4 N stripes of 32

    const uint32_t As_base = (uint32_t)__cvta_generic_to_shared(As);
    const uint32_t Bs_base = (uint32_t)__cvta_generic_to_shared(Bs);

    const int nch   = (NCHUNKS - pidx + pairs - 1) / pairs;
    const int total = nch * 4;           // 64-K slabs for this CTA

    // ---- B staging: slab = 64 rows x 128 cols fp32 = 2048 float4 ----
    const float4* membase = reinterpret_cast<const float4*>(memory);
    float4 br[2];

    auto ldg_half = [&](int tt, int h) {
        const int c  = pidx + (tt >> 2) * pairs;
        const int kc = tt & 3;
        const float4* src = membase + (size_t)(kc * 64) * (NCOL / 4) + (size_t)c * 32;
#pragma unroll
        for (int q = 0; q < 2; q++) {
            int i = tid + (q + 2 * h) * GT;
            br[q] = __ldg(&src[(size_t)(i >> 5) * (NCOL / 4) + (i & 31)]);
        }
    };
    auto sts_half = [&](int tt, int h) {
        const int buf = tt & 1;
#pragma unroll
        for (int q = 0; q < 2; q++) {
            int i = tid + (q + 2 * h) * GT;
            int r = i >> 5, c4 = i & 31;
            __half2 h0 = __floats2half2_rn(br[q].x, br[q].y);
            __half2 h1 = __floats2half2_rn(br[q].z, br[q].w);
            uint2* dp = reinterpret_cast<uint2*>(Bs + buf * B_SLAB + r * BPAD + c4 * 4);
            *dp = make_uint2(*reinterpret_cast<uint32_t*>(&h0),
                             *reinterpret_cast<uint32_t*>(&h1));
        }
    };
    auto prefetch_slab = [&](int tt) {
        const int c  = pidx + (tt >> 2) * pairs;
        const int kc = tt & 3;
        const float* p = memory + (size_t)(kc * 64 + (tid >> 3)) * NCOL
                       + (size_t)c * NCHUNK + (tid & 7) * 16;
        prefetch_l2(p);
    };

    // ---- PDL phase A: g_W-independent prologue (overlaps topk tail) ----
    if (total > 2) prefetch_slab(2);
    ldg_half(0, 0); sts_half(0, 0);
    ldg_half(0, 1); sts_half(0, 1);
    if (total > 1) ldg_half(1, 0);

    // ---- PDL phase B: wait for topk grid, then load A (cp.async) ----
    asm volatile("griddepcontrol.wait;" ::: "memory");
    {
        const __half* srcA = g_W + (size_t)(mhalf * MTILE) * MEM;
#pragma unroll
        for (int j = 0; j < 16; j++) {
            int i = tid + j * GT;                // 8192 granules of 16B
            int m = i >> 5, gs = i & 31;
            uint32_t sa = As_base + (uint32_t)(m * 512 + ((gs ^ (m & 7)) << 4));
            const __half* gp = srcA + m * MEM + gs * 8;
            asm volatile("cp.async.cg.shared.global [%0], [%1], 16;" :: "r"(sa), "l"(gp) : "memory");
        }
        asm volatile("cp.async.commit_group;" ::: "memory");
        asm volatile("cp.async.wait_group 0;" ::: "memory");
    }
    __syncthreads();

    // A fragment row bases (swizzle applied per-k at use)
    uint32_t a_row[4], am7[4];
#pragma unroll
    for (int mi = 0; mi < 4; mi++) {
        int m = mw + mi * 16 + (lane & 15);
        a_row[mi] = As_base + (uint32_t)(m * 512);
        am7[mi]   = (uint32_t)(m & 7);
    }
    // B ldmatrix lane offset (bytes within a slab)
    const int bgrp = lane >> 3;
    const uint32_t b_lane_off =
        (uint32_t)(((bgrp & 1) * 8 + (lane & 7)) * (BPAD * 2) + (nw + (bgrp >> 1) * 8) * 2);

    float d[4][4][4];
#pragma unroll
    for (int mi = 0; mi < 4; mi++)
#pragma unroll
        for (int ni = 0; ni < 4; ni++)
#pragma unroll
            for (int r = 0; r < 4; r++) d[mi][ni][r] = 0.f;

    int c = pidx;
    for (int t = 0; t < total; t++) {
        const int  kc   = t & 3;
        const bool more = (t + 1 < total);
        const uint32_t bbase = Bs_base + (uint32_t)((t & 1) * B_SLAB * 2) + b_lane_off;

#pragma unroll
        for (int ks = 0; ks < 4; ks++) {
            // staging schedule: every LDG gets a 2-ks window; slabs are
            // L2-prefetched 3 ahead so LDG hits L2 (~250cyc << window).
            if (ks == 0 && more) { sts_half(t + 1, 0); ldg_half(t + 1, 1); }
            if (ks == 1 && t + 3 < total) prefetch_slab(t + 3);
            if (ks == 2 && more) { sts_half(t + 1, 1); if (t + 2 < total) ldg_half(t + 2, 0); }

            uint32_t bf[8];
            ldsm_x4_t(bf,     bbase + ks * (16 * BPAD * 2));
            ldsm_x4_t(bf + 4, bbase + ks * (16 * BPAD * 2) + 32);
            const uint32_t gk = (uint32_t)(kc * 8 + ks * 2 + gl);
#pragma unroll
            for (int mi = 0; mi < 4; mi++) {
                uint32_t a[4];
                ldsm_x4(a, a_row[mi] + ((gk ^ am7[mi]) << 4));
                mma16816(d[mi][0], a[0], a[1], a[2], a[3], bf[0], bf[1]);
                mma16816(d[mi][1], a[0], a[1], a[2], a[3], bf[2], bf[3]);
                mma16816(d[mi][2], a[0], a[1], a[2], a[3], bf[4], bf[5]);
                mma16816(d[mi][3], a[0], a[1], a[2], a[3], bf[6], bf[7]);
            }
        }

        if (kc == 3) {
            // epilogue for chunk c: streaming stores, reset accumulators
            const size_t cbase = (size_t)c * NCHUNK;
            const int mbase = mhalf * MTILE;
#pragma unroll
            for (int mi = 0; mi < 4; mi++) {
                const int r0 = mbase + mw + mi * 16 + g;
#pragma unroll
                for (int ni = 0; ni < 4; ni++) {
                    const size_t col = cbase + nw + ni * 8 + tg * 2;
                    stg_cs_v2(out + (size_t)r0 * NCOL + col,
                              make_float2(d[mi][ni][0], d[mi][ni][1]));
                    stg_cs_v2(out + (size_t)(r0 + 8) * NCOL + col,
                              make_float2(d[mi][ni][2], d[mi][ni][3]));
#pragma unroll
                    for (int r = 0; r < 4; r++) d[mi][ni][r] = 0.f;
                }
            }
            c += pairs;
        }

        __syncthreads();   // next slab's fp16 buffer fully written
    }
}

// ---------------------------------------------------------------------------
extern "C" void kernel_launch(void* const* d_in, const int* in_sizes, int n_in,
                              void* d_out, int out_size) {
    const float* features = (const float*)d_in[0];
    const float* keys     = (const float*)d_in[1];
    const float* memory   = (const float*)d_in[2];
    float*       out      = (float*)d_out;

    int sms = 148;
    cudaDeviceGetAttribute(&sms, cudaDevAttrMultiProcessorCount, 0);

    cudaFuncSetAttribute(gemm_kernel,
                         cudaFuncAttributeMaxDynamicSharedMemorySize, DYN_SMEM);

    topk_kernel<<<BATCH / 4, 256>>>(features, keys);

    // PDL launch: gemm CTAs may start while topk drains; they block at
    // griddepcontrol.wait until all topk CTAs signal launch_dependents.
    cudaLaunchConfig_t cfg = {};
    cfg.gridDim  = dim3(2 * sms);
    cfg.blockDim = dim3(GT);
    cfg.dynamicSmemBytes = DYN_SMEM;
    cfg.stream = 0;
    cudaLaunchAttribute attrs[1];
    attrs[0].id = cudaLaunchAttributeProgrammaticStreamSerialization;
    attrs[0].val.programmaticStreamSerializationAllowed = 1;
    cfg.attrs = attrs;
    cfg.numAttrs = 1;
    cudaLaunchKernelEx(&cfg, gemm_kernel, memory, out, sms);
}